// round 16
// baseline (speedup 1.0000x reference)
#include <cuda_runtime.h>
#include <cuda_fp16.h>
#include <math.h>

#define NN_MAX 100000
#define EE_MAX 1600000
#define DF 128

#define SCAN_T 256
#define SCAN_C 4
#define SCAN_TILE (SCAN_T * SCAN_C)
#define SCAN_NBMAX ((NN_MAX + 1 + SCAN_TILE - 1) / SCAN_TILE + 1)

// ---------------- scratch (device globals: no allocation allowed) ----------------
__device__ int   g_idx64;
__device__ int   g_cnt[NN_MAX];
__device__ int   g_rowptr[NN_MAX + 1];
__device__ int   g_cursor[NN_MAX];
__device__ int   g_srcs[EE_MAX];
__device__ float g_dinv[NN_MAX];
__device__ int   g_bsum[SCAN_NBMAX];
__device__ int   g_boff[SCAN_NBMAX];
__device__ __half g_z0h[(size_t)NN_MAX * DF];
__device__ __half g_z1h[(size_t)NN_MAX * DF];
__device__ __half g_zsh[(size_t)NN_MAX * DF];
__device__ __half g_wh[448 * DF];               // W1|W2|fcW1|fcW2 as fp16
__device__ float g_zs[(size_t)NN_MAX * DF];
__device__ float g_res[(size_t)NN_MAX * 64];
__device__ float g_zerob[DF];   // stays zero (bss)

// ---------------- helpers ----------------
__device__ __forceinline__ long long ldidx(const void* p, long long i, int is64) {
    return is64 ? ((const long long*)p)[i] : (long long)(((const int*)p)[i]);
}

__global__ void k_detect(const void* ei, long long E) {
    __shared__ unsigned sm[256];
    const unsigned* w = (const unsigned*)ei;
    int tid = threadIdx.x;
    int lim = (int)(E - 1 < 1024 ? E - 1 : 1024);
    unsigned acc = 0;
    for (int i = tid; i < lim; i += 256) acc |= w[2 * i + 1];
    sm[tid] = acc;
    __syncthreads();
    for (int d = 128; d; d >>= 1) {
        if (tid < d) sm[tid] |= sm[tid + d];
        __syncthreads();
    }
    if (tid == 0) g_idx64 = (sm[0] == 0u) ? 1 : 0;
}

__global__ void k_count(const void* ei, long long E) {
    int is64 = g_idx64;
    long long stride = (long long)gridDim.x * blockDim.x;
    for (long long e = (long long)blockIdx.x * blockDim.x + threadIdx.x; e < E; e += stride) {
        int dst = (int)ldidx(ei, E + e, is64);
        atomicAdd(&g_cnt[dst], 1);
    }
}

// ---------------- 3-phase chip-wide exclusive scan of g_cnt ----------------
__global__ void k_scan_a(int n) {
    __shared__ int sm[SCAN_T];
    int tid = threadIdx.x;
    int base = blockIdx.x * SCAN_TILE + tid * SCAN_C;
    int s = 0;
#pragma unroll
    for (int i = 0; i < SCAN_C; i++) {
        int idx = base + i;
        if (idx < n) s += g_cnt[idx];
    }
    sm[tid] = s;
    __syncthreads();
    for (int d = SCAN_T / 2; d; d >>= 1) {
        if (tid < d) sm[tid] += sm[tid + d];
        __syncthreads();
    }
    if (tid == 0) g_bsum[blockIdx.x] = sm[0];
}

__global__ void k_scan_b(int nb) {
    __shared__ int sm[128];
    int tid = threadIdx.x;
    int v = (tid < nb) ? g_bsum[tid] : 0;
    sm[tid] = v;
    __syncthreads();
    for (int d = 1; d < 128; d <<= 1) {
        int t = (tid >= d) ? sm[tid - d] : 0;
        __syncthreads();
        sm[tid] += t;
        __syncthreads();
    }
    if (tid < nb) g_boff[tid] = sm[tid] - v;
}

__global__ void k_scan_c(int n) {
    __shared__ int sm[SCAN_T];
    int tid = threadIdx.x;
    int base = blockIdx.x * SCAN_TILE + tid * SCAN_C;
    int c[SCAN_C];
    int s = 0;
#pragma unroll
    for (int i = 0; i < SCAN_C; i++) {
        int idx = base + i;
        c[i] = (idx < n) ? g_cnt[idx] : 0;
        s += c[i];
    }
    sm[tid] = s;
    __syncthreads();
    for (int d = 1; d < SCAN_T; d <<= 1) {
        int t = (tid >= d) ? sm[tid - d] : 0;
        __syncthreads();
        sm[tid] += t;
        __syncthreads();
    }
    int run = g_boff[blockIdx.x] + sm[tid] - s;
#pragma unroll
    for (int i = 0; i < SCAN_C; i++) {
        int idx = base + i;
        if (idx < n) {
            g_rowptr[idx] = run;
            g_cursor[idx] = run;
            g_dinv[idx] = rsqrtf((float)(c[i] + 1));
            run += c[i];
        } else if (idx == n) {
            g_rowptr[n] = run;
        }
    }
}

__global__ void k_fill(const void* ei, long long E) {
    int is64 = g_idx64;
    long long stride = (long long)gridDim.x * blockDim.x;
    for (long long e = (long long)blockIdx.x * blockDim.x + threadIdx.x; e < E; e += stride) {
        int src = (int)ldidx(ei, e, is64);
        int dst = (int)ldidx(ei, E + e, is64);
        int p = atomicAdd(&g_cursor[dst], 1);
        g_srcs[p] = src;
    }
}

// weights -> fp16
__global__ void k_wconv(const float* __restrict__ W1, const float* __restrict__ W2,
                        const float* __restrict__ f1, const float* __restrict__ f2) {
    int i = blockIdx.x * blockDim.x + threadIdx.x;
    if (i >= 448 * DF) return;
    int r = i >> 7;
    float v;
    if (r < 128) v = W1[i];
    else if (r < 256) v = W2[i - 128 * DF];
    else if (r < 384) v = f1[i - 256 * DF];
    else v = f2[i - 384 * DF];
    g_wh[i] = __float2half_rn(v);
}

// ---------------- fp16 tensor-core GEMM (W already fp16) ----------------
#define LDA 36

__device__ __forceinline__ unsigned f2h2(float a, float b) {
    __half2 h = __floats2half2_rn(a, b);
    return *(unsigned*)&h;
}

__device__ __forceinline__ void mma_f16(float* d, const unsigned* a, const unsigned* b) {
    asm volatile(
        "mma.sync.aligned.m16n8k16.row.col.f32.f16.f16.f32 "
        "{%0,%1,%2,%3}, {%4,%5,%6,%7}, {%8,%9}, {%0,%1,%2,%3};\n"
        : "+f"(d[0]), "+f"(d[1]), "+f"(d[2]), "+f"(d[3])
        : "r"(a[0]), "r"(a[1]), "r"(a[2]), "r"(a[3]), "r"(b[0]), "r"(b[1]));
}

__device__ __forceinline__ float act_apply(float v, int ACT) {
    if (ACT == 1) return v > 0.f ? v : expm1f(v);
    return v;
}

// INH: A source half (else float). OUTH: store half (else float). row0: row offset.
template <int ACT, int INH, int OUTH>
__global__ __launch_bounds__(256, 2) void k_gemm_f16(
    const void* __restrict__ Av, const __half* __restrict__ Wh,
    const float* __restrict__ bias, void* __restrict__ Cv, int row0, int M) {
    __shared__ unsigned As[128 * LDA];
    __shared__ unsigned Ws[128 * LDA];
    int tid = threadIdx.x;
    int lane = tid & 31, warp = tid >> 5;
    int mw = warp & 1, nw = warp >> 1;
    int rowBase = row0 + blockIdx.x * 128;
    int g = lane >> 2, tig = lane & 3;

    float acc[4][4][4];
#pragma unroll
    for (int i = 0; i < 4; i++)
#pragma unroll
        for (int j = 0; j < 4; j++)
#pragma unroll
            for (int q = 0; q < 4; q++) acc[i][j][q] = 0.f;

#pragma unroll
    for (int ch = 0; ch < 2; ch++) {
        int kh = ch * 64;
#pragma unroll
        for (int i = 0; i < 4; i++) {
            int id = tid + i * 256;
            int r = id >> 3, c8 = (id & 7) * 4;
            if (INH) {
                uint4 u = make_uint4(0, 0, 0, 0);
                if (rowBase + r < M)
                    u = *(const uint4*)((const unsigned*)Av + (size_t)(rowBase + r) * (DF / 2) + kh / 2 + c8);
                *(uint4*)&As[r * LDA + c8] = u;
            } else {
                float4 v0 = make_float4(0.f, 0.f, 0.f, 0.f), v1 = v0;
                if (rowBase + r < M) {
                    const float* ap = (const float*)Av + (size_t)(rowBase + r) * DF + kh + c8 * 2;
                    v0 = *(const float4*)(ap);
                    v1 = *(const float4*)(ap + 4);
                }
                *(uint4*)&As[r * LDA + c8] = make_uint4(
                    f2h2(v0.x, v0.y), f2h2(v0.z, v0.w), f2h2(v1.x, v1.y), f2h2(v1.z, v1.w));
            }
            uint4 uw = *(const uint4*)((const unsigned*)Wh + (size_t)r * (DF / 2) + kh / 2 + c8);
            *(uint4*)&Ws[r * LDA + c8] = uw;
        }
        __syncthreads();

#pragma unroll
        for (int ks = 0; ks < 4; ks++) {
            int k0 = ks * 8;
            unsigned afr[4][4], bfr[4][2];
#pragma unroll
            for (int ma = 0; ma < 4; ma++) {
                int row = mw * 64 + ma * 16;
                afr[ma][0] = As[(row + g) * LDA + k0 + tig];
                afr[ma][1] = As[(row + g + 8) * LDA + k0 + tig];
                afr[ma][2] = As[(row + g) * LDA + k0 + tig + 4];
                afr[ma][3] = As[(row + g + 8) * LDA + k0 + tig + 4];
            }
#pragma unroll
            for (int na = 0; na < 4; na++) {
                int colw = nw * 32 + na * 8;
                bfr[na][0] = Ws[(colw + g) * LDA + k0 + tig];
                bfr[na][1] = Ws[(colw + g) * LDA + k0 + tig + 4];
            }
#pragma unroll
            for (int ma = 0; ma < 4; ma++)
#pragma unroll
                for (int na = 0; na < 4; na++) mma_f16(acc[ma][na], afr[ma], bfr[na]);
        }
        __syncthreads();
    }

#pragma unroll
    for (int ma = 0; ma < 4; ma++) {
        int r0 = rowBase + mw * 64 + ma * 16 + g;
        int r1 = r0 + 8;
#pragma unroll
        for (int na = 0; na < 4; na++) {
            int cc = nw * 32 + na * 8 + 2 * tig;
            float b0 = bias[cc], b1 = bias[cc + 1];
            float x0 = act_apply(acc[ma][na][0] + b0, ACT);
            float x1 = act_apply(acc[ma][na][1] + b1, ACT);
            float x2 = act_apply(acc[ma][na][2] + b0, ACT);
            float x3 = act_apply(acc[ma][na][3] + b1, ACT);
            if (OUTH) {
                __half* C = (__half*)Cv;
                if (r0 < M) *(__half2*)(C + (size_t)r0 * DF + cc) = __floats2half2_rn(x0, x1);
                if (r1 < M) *(__half2*)(C + (size_t)r1 * DF + cc) = __floats2half2_rn(x2, x3);
            } else {
                float* C = (float*)Cv;
                if (r0 < M) *(float2*)(C + (size_t)r0 * DF + cc) = make_float2(x0, x1);
                if (r1 < M) *(float2*)(C + (size_t)r1 * DF + cc) = make_float2(x2, x3);
            }
        }
    }
}

// ---------------- fp16 final GEMM (N=64) + fused log_softmax ----------------
__global__ __launch_bounds__(256, 2) void k_gemm_lsm_f16(
    const __half* __restrict__ A, const __half* __restrict__ Wh,
    const float* __restrict__ bias, float* __restrict__ out, int row0, int M) {
    __shared__ unsigned As[128 * LDA];
    __shared__ unsigned Ws[64 * LDA];
    int tid = threadIdx.x;
    int lane = tid & 31, warp = tid >> 5;
    int rowBase = row0 + blockIdx.x * 128;
    int g = lane >> 2, tig = lane & 3;

    float acc[8][4];
#pragma unroll
    for (int j = 0; j < 8; j++)
#pragma unroll
        for (int q = 0; q < 4; q++) acc[j][q] = 0.f;

#pragma unroll
    for (int ch = 0; ch < 2; ch++) {
        int kh = ch * 64;
#pragma unroll
        for (int i = 0; i < 4; i++) {
            int id = tid + i * 256;
            int r = id >> 3, c8 = (id & 7) * 4;
            uint4 u = make_uint4(0, 0, 0, 0);
            if (rowBase + r < M)
                u = *(const uint4*)((const unsigned*)A + (size_t)(rowBase + r) * (DF / 2) + kh / 2 + c8);
            *(uint4*)&As[r * LDA + c8] = u;
        }
#pragma unroll
        for (int i = 0; i < 2; i++) {
            int id = tid + i * 256;
            int r = id >> 3, c8 = (id & 7) * 4;
            uint4 uw = *(const uint4*)((const unsigned*)Wh + (size_t)r * (DF / 2) + kh / 2 + c8);
            *(uint4*)&Ws[r * LDA + c8] = uw;
        }
        __syncthreads();

#pragma unroll
        for (int ks = 0; ks < 4; ks++) {
            int k0 = ks * 8;
            unsigned afr[4], bfr[8][2];
            int row = warp * 16;
            afr[0] = As[(row + g) * LDA + k0 + tig];
            afr[1] = As[(row + g + 8) * LDA + k0 + tig];
            afr[2] = As[(row + g) * LDA + k0 + tig + 4];
            afr[3] = As[(row + g + 8) * LDA + k0 + tig + 4];
#pragma unroll
            for (int na = 0; na < 8; na++) {
                int colw = na * 8;
                bfr[na][0] = Ws[(colw + g) * LDA + k0 + tig];
                bfr[na][1] = Ws[(colw + g) * LDA + k0 + tig + 4];
            }
#pragma unroll
            for (int na = 0; na < 8; na++) mma_f16(acc[na], afr, bfr[na]);
        }
        __syncthreads();
    }

    float v0[16], v1[16];
#pragma unroll
    for (int na = 0; na < 8; na++) {
        int cc = na * 8 + 2 * tig;
        float b0 = bias[cc], b1 = bias[cc + 1];
        v0[na * 2 + 0] = acc[na][0] + b0;
        v0[na * 2 + 1] = acc[na][1] + b1;
        v1[na * 2 + 0] = acc[na][2] + b0;
        v1[na * 2 + 1] = acc[na][3] + b1;
    }
    float m0 = v0[0], m1 = v1[0];
#pragma unroll
    for (int i = 1; i < 16; i++) { m0 = fmaxf(m0, v0[i]); m1 = fmaxf(m1, v1[i]); }
#pragma unroll
    for (int d = 1; d < 4; d <<= 1) {
        m0 = fmaxf(m0, __shfl_xor_sync(0xffffffffu, m0, d));
        m1 = fmaxf(m1, __shfl_xor_sync(0xffffffffu, m1, d));
    }
    float s0 = 0.f, s1 = 0.f;
#pragma unroll
    for (int i = 0; i < 16; i++) { s0 += expf(v0[i] - m0); s1 += expf(v1[i] - m1); }
#pragma unroll
    for (int d = 1; d < 4; d <<= 1) {
        s0 += __shfl_xor_sync(0xffffffffu, s0, d);
        s1 += __shfl_xor_sync(0xffffffffu, s1, d);
    }
    float ls0 = m0 + logf(s0), ls1 = m1 + logf(s1);

    int r0 = rowBase + warp * 16 + g;
    int r1 = r0 + 8;
#pragma unroll
    for (int na = 0; na < 8; na++) {
        int cc = na * 8 + 2 * tig;
        if (r0 < M) {
            float2 o = make_float2(v0[na * 2] - ls0, v0[na * 2 + 1] - ls0);
            *(float2*)(out + (size_t)r0 * 64 + cc) = o;
        }
        if (r1 < M) {
            float2 o = make_float2(v1[na * 2] - ls1, v1[na * 2 + 1] - ls1);
            *(float2*)(out + (size_t)r1 * 64 + cc) = o;
        }
    }
}

// ---------------- aggregation over fp16 features (node range [w0, wEnd)) ----------
__global__ void k_agg_h(const uint2* __restrict__ zin, float* __restrict__ outf,
                        __half* __restrict__ outh, const float* __restrict__ bias,
                        int w0, int wEnd, int relu) {
    int w = w0 + ((blockIdx.x * blockDim.x + threadIdx.x) >> 5);
    int lane = threadIdx.x & 31;
    if (w >= wEnd) return;
    float di = g_dinv[w];
    uint2 su = zin[(size_t)w * 32 + lane];
    float2 a0 = __half22float2(*(__half2*)&su.x);
    float2 a1 = __half22float2(*(__half2*)&su.y);
    float sw = di * di;
    float4 acc;
    acc.x = sw * a0.x; acc.y = sw * a0.y; acc.z = sw * a1.x; acc.w = sw * a1.y;
    int e = g_rowptr[w], end = g_rowptr[w + 1];
    for (; e + 4 <= end; e += 4) {
        int s[4];
        float wt[4];
#pragma unroll
        for (int i = 0; i < 4; i++) s[i] = g_srcs[e + i];
#pragma unroll
        for (int i = 0; i < 4; i++) wt[i] = di * g_dinv[s[i]];
        uint2 u[4];
#pragma unroll
        for (int i = 0; i < 4; i++) u[i] = zin[(size_t)s[i] * 32 + lane];
#pragma unroll
        for (int i = 0; i < 4; i++) {
            float2 f0 = __half22float2(*(__half2*)&u[i].x);
            float2 f1 = __half22float2(*(__half2*)&u[i].y);
            acc.x = fmaf(wt[i], f0.x, acc.x); acc.y = fmaf(wt[i], f0.y, acc.y);
            acc.z = fmaf(wt[i], f1.x, acc.z); acc.w = fmaf(wt[i], f1.y, acc.w);
        }
    }
    for (; e < end; e++) {
        int s = g_srcs[e];
        float wt = di * g_dinv[s];
        uint2 u = zin[(size_t)s * 32 + lane];
        float2 f0 = __half22float2(*(__half2*)&u.x);
        float2 f1 = __half22float2(*(__half2*)&u.y);
        acc.x = fmaf(wt, f0.x, acc.x); acc.y = fmaf(wt, f0.y, acc.y);
        acc.z = fmaf(wt, f1.x, acc.z); acc.w = fmaf(wt, f1.y, acc.w);
    }
    float4 b = ((const float4*)bias)[lane];
    acc.x += b.x; acc.y += b.y; acc.z += b.z; acc.w += b.w;
    if (relu) {
        acc.x = fmaxf(acc.x, 0.f); acc.y = fmaxf(acc.y, 0.f);
        acc.z = fmaxf(acc.z, 0.f); acc.w = fmaxf(acc.w, 0.f);
    }
    if (outf) ((float4*)outf)[(size_t)w * 32 + lane] = acc;
    if (outh) {
        uint2 o;
        __half2 h0 = __floats2half2_rn(acc.x, acc.y);
        __half2 h1 = __floats2half2_rn(acc.z, acc.w);
        o.x = *(unsigned*)&h0; o.y = *(unsigned*)&h1;
        ((uint2*)outh)[(size_t)w * 32 + lane] = o;
    }
}

// ---------------- launcher ----------------
extern "C" void kernel_launch(void* const* d_in, const int* in_sizes, int n_in,
                              void* d_out, int out_size) {
    const float* x    = (const float*)d_in[0];
    const void*  ei   = d_in[1];
    const float* W1   = (const float*)d_in[2];
    const float* b1   = (const float*)d_in[3];
    const float* W2   = (const float*)d_in[4];
    const float* b2   = (const float*)d_in[5];
    const float* fcW1 = (const float*)d_in[6];
    const float* fcb1 = (const float*)d_in[7];
    const float* fcW2 = (const float*)d_in[8];
    const float* fcb2 = (const float*)d_in[9];

    int N = in_sizes[0] / DF;
    long long E = (long long)in_sizes[1] / 2;

    float *zsb, *resb, *zb;
    __half *z0h, *z1h, *zsh, *wh;
    int* cntp;
    cudaGetSymbolAddress((void**)&z0h, g_z0h);
    cudaGetSymbolAddress((void**)&z1h, g_z1h);
    cudaGetSymbolAddress((void**)&zsh, g_zsh);
    cudaGetSymbolAddress((void**)&wh,  g_wh);
    cudaGetSymbolAddress((void**)&zsb, g_zs);
    cudaGetSymbolAddress((void**)&resb, g_res);
    cudaGetSymbolAddress((void**)&zb,  g_zerob);
    cudaGetSymbolAddress((void**)&cntp, g_cnt);

    const __half* whW1 = wh;
    const __half* whW2 = wh + 128 * DF;
    const __half* whF1 = wh + 256 * DF;
    const __half* whF2 = wh + 384 * DF;

    // Output layout: tuple (zs [N,128], res [N,64]) concatenated.
    float* zs_out;
    float* res_out;
    long long need_both = (long long)N * (DF + 64);
    if ((long long)out_size >= need_both) {
        zs_out = (float*)d_out;
        res_out = (float*)d_out + (size_t)N * DF;
    } else if (out_size == N * 64) {
        zs_out = zsb;
        res_out = (float*)d_out;
    } else {
        zs_out = (float*)d_out;
        res_out = resb;
    }

    int nb_e = (int)((E + 511) / 512);
    int nb_s = (N + 1 + SCAN_TILE - 1) / SCAN_TILE;

    // row-aligned half split (multiple of 128)
    int Nlo = ((N / 2 + 127) / 128) * 128;
    if (Nlo > N) Nlo = N;
    int Nhi = N - Nlo;
    int nbw_lo = (Nlo * 32 + 255) / 256;
    int nbw_hi = (Nhi * 32 + 255) / 256;
    int nbg_lo = (Nlo + 127) / 128;
    int nbg_hi = (Nhi + 127) / 128;
    int nb_g   = (N + 127) / 128;

    static cudaStream_t s1 = nullptr, s2 = nullptr;
    static cudaEvent_t evFork = nullptr, evJoin = nullptr;
    static cudaEvent_t evA1L, evA1H, evG2H, evA2L, evA2H, evG3L, evG3H;
    if (s2 == nullptr) {
        cudaStreamCreateWithFlags(&s1, cudaStreamNonBlocking);
        cudaStreamCreateWithFlags(&s2, cudaStreamNonBlocking);
        cudaEventCreateWithFlags(&evFork, cudaEventDisableTiming);
        cudaEventCreateWithFlags(&evJoin, cudaEventDisableTiming);
        cudaEventCreateWithFlags(&evA1L, cudaEventDisableTiming);
        cudaEventCreateWithFlags(&evA1H, cudaEventDisableTiming);
        cudaEventCreateWithFlags(&evG2H, cudaEventDisableTiming);
        cudaEventCreateWithFlags(&evA2L, cudaEventDisableTiming);
        cudaEventCreateWithFlags(&evA2H, cudaEventDisableTiming);
        cudaEventCreateWithFlags(&evG3L, cudaEventDisableTiming);
        cudaEventCreateWithFlags(&evG3H, cudaEventDisableTiming);
    }

    // fork: preprocessing branch on s2, gemm branch on default stream
    cudaEventRecord(evFork, 0);
    cudaStreamWaitEvent(s2, evFork, 0);

    // s2: graph preprocessing (CSR build)
    k_detect<<<1, 256, 0, s2>>>(ei, E);
    cudaMemsetAsync(cntp, 0, (size_t)N * sizeof(int), s2);
    k_count<<<nb_e, 256, 0, s2>>>(ei, E);
    k_scan_a<<<nb_s, SCAN_T, 0, s2>>>(N);
    k_scan_b<<<1, 128, 0, s2>>>(nb_s);
    k_scan_c<<<nb_s, SCAN_T, 0, s2>>>(N);
    k_fill<<<nb_e, 256, 0, s2>>>(ei, E);
    cudaEventRecord(evJoin, s2);

    // default: weight conversion + gemm1 (x -> z0h)
    k_wconv<<<(448 * DF + 255) / 256, 256>>>(W1, W2, fcW1, fcW2);
    k_gemm_f16<0, 0, 1><<<nb_g, 256>>>(x, whW1, zb, z0h, 0, N);

    // join
    cudaStreamWaitEvent(0, evJoin, 0);

    // agg1 (z0h -> z1h, relu) in halves on default stream
    k_agg_h<<<nbw_lo, 256>>>((const uint2*)z0h, nullptr, z1h, b1, 0, Nlo, 1);
    cudaEventRecord(evA1L, 0);
    if (Nhi > 0) k_agg_h<<<nbw_hi, 256>>>((const uint2*)z0h, nullptr, z1h, b1, Nlo, N, 1);
    cudaEventRecord(evA1H, 0);

    // gemm2 (z1h -> zsh) halves on s1, pipelined against agg1_hi
    cudaStreamWaitEvent(s1, evA1L, 0);
    k_gemm_f16<0, 1, 1><<<nbg_lo, 256, 0, s1>>>(z1h, whW2, zb, zsh, 0, N);
    cudaStreamWaitEvent(s1, evA1H, 0);
    if (nbg_hi > 0) k_gemm_f16<0, 1, 1><<<nbg_hi, 256, 0, s1>>>(z1h, whW2, zb, zsh, Nlo, N);
    cudaEventRecord(evG2H, s1);

    // agg2 (zsh -> zs_out fp32 + z0h half) halves on default stream (needs ALL of gemm2)
    cudaStreamWaitEvent(0, evG2H, 0);
    k_agg_h<<<nbw_lo, 256>>>((const uint2*)zsh, zs_out, z0h, b2, 0, Nlo, 0);
    cudaEventRecord(evA2L, 0);
    if (Nhi > 0) k_agg_h<<<nbw_hi, 256>>>((const uint2*)zsh, zs_out, z0h, b2, Nlo, N, 0);
    cudaEventRecord(evA2H, 0);

    // gemm3 / fc1 elu (z0h -> z1h) halves on s1, pipelined against agg2_hi
    cudaStreamWaitEvent(s1, evA2L, 0);
    k_gemm_f16<1, 1, 1><<<nbg_lo, 256, 0, s1>>>(z0h, whF1, fcb1, z1h, 0, N);
    cudaEventRecord(evG3L, s1);
    cudaStreamWaitEvent(s1, evA2H, 0);
    if (nbg_hi > 0) k_gemm_f16<1, 1, 1><<<nbg_hi, 256, 0, s1>>>(z0h, whF1, fcb1, z1h, Nlo, N);
    cudaEventRecord(evG3H, s1);

    // lsm (z1h -> res_out) halves on default stream, pipelined against gemm3_hi
    cudaStreamWaitEvent(0, evG3L, 0);
    k_gemm_lsm_f16<<<nbg_lo, 256>>>(z1h, whF2, fcb2, res_out, 0, N);
    cudaStreamWaitEvent(0, evG3H, 0);
    if (nbg_hi > 0) k_gemm_lsm_f16<<<nbg_hi, 256>>>(z1h, whF2, fcb2, res_out, Nlo, N);
}

// round 17
// speedup vs baseline: 1.1072x; 1.1072x over previous
#include <cuda_runtime.h>
#include <cuda_fp16.h>
#include <math.h>

#define NN_MAX 100000
#define EE_MAX 1600000
#define DF 128

#define SCAN_T 256
#define SCAN_C 4
#define SCAN_TILE (SCAN_T * SCAN_C)
#define SCAN_NBMAX ((NN_MAX + 1 + SCAN_TILE - 1) / SCAN_TILE + 1)

// ---------------- scratch (device globals: no allocation allowed) ----------------
__device__ int   g_idx64;
__device__ int   g_cnt[NN_MAX];
__device__ int   g_rowptr[NN_MAX + 1];
__device__ int   g_cursor[NN_MAX];
__device__ int   g_srcs[EE_MAX];
__device__ float g_dinv[NN_MAX];
__device__ int   g_bsum[SCAN_NBMAX];
__device__ int   g_boff[SCAN_NBMAX];
__device__ __half g_z0h[(size_t)NN_MAX * DF];
__device__ __half g_z1h[(size_t)NN_MAX * DF];
__device__ __half g_zsh[(size_t)NN_MAX * DF];
__device__ __half g_wh[448 * DF];               // W1|W2|fcW1|fcW2 as fp16
__device__ float g_zs[(size_t)NN_MAX * DF];
__device__ float g_res[(size_t)NN_MAX * 64];
__device__ float g_zerob[DF];   // stays zero (bss)

// ---------------- helpers ----------------
__device__ __forceinline__ long long ldidx(const void* p, long long i, int is64) {
    return is64 ? ((const long long*)p)[i] : (long long)(((const int*)p)[i]);
}

__global__ void k_detect(const void* ei, long long E) {
    __shared__ unsigned sm[256];
    const unsigned* w = (const unsigned*)ei;
    int tid = threadIdx.x;
    int lim = (int)(E - 1 < 1024 ? E - 1 : 1024);
    unsigned acc = 0;
    for (int i = tid; i < lim; i += 256) acc |= w[2 * i + 1];
    sm[tid] = acc;
    __syncthreads();
    for (int d = 128; d; d >>= 1) {
        if (tid < d) sm[tid] |= sm[tid + d];
        __syncthreads();
    }
    if (tid == 0) g_idx64 = (sm[0] == 0u) ? 1 : 0;
}

// count: vectorized int64 path (uint4 = 2 dsts), 4 edges/thread/iter
__global__ void k_count(const void* ei, long long E) {
    int is64 = g_idx64;
    if (is64 && ((E & 1) == 0)) {
        const uint4* d4 = (const uint4*)((const long long*)ei + E);  // dst row
        long long P = E >> 1;                                        // pairs
        long long stride = (long long)gridDim.x * blockDim.x;
        long long i = (long long)blockIdx.x * blockDim.x + threadIdx.x;
        for (; i + stride < P; i += 2 * stride) {
            uint4 a = d4[i];
            uint4 b = d4[i + stride];
            atomicAdd(&g_cnt[a.x], 1);
            atomicAdd(&g_cnt[a.z], 1);
            atomicAdd(&g_cnt[b.x], 1);
            atomicAdd(&g_cnt[b.z], 1);
        }
        for (; i < P; i += stride) {
            uint4 a = d4[i];
            atomicAdd(&g_cnt[a.x], 1);
            atomicAdd(&g_cnt[a.z], 1);
        }
    } else {
        long long stride = (long long)gridDim.x * blockDim.x;
        for (long long e = (long long)blockIdx.x * blockDim.x + threadIdx.x; e < E; e += stride) {
            int dst = (int)ldidx(ei, E + e, is64);
            atomicAdd(&g_cnt[dst], 1);
        }
    }
}

// ---------------- 3-phase chip-wide exclusive scan of g_cnt ----------------
__global__ void k_scan_a(int n) {
    __shared__ int sm[SCAN_T];
    int tid = threadIdx.x;
    int base = blockIdx.x * SCAN_TILE + tid * SCAN_C;
    int s = 0;
#pragma unroll
    for (int i = 0; i < SCAN_C; i++) {
        int idx = base + i;
        if (idx < n) s += g_cnt[idx];
    }
    sm[tid] = s;
    __syncthreads();
    for (int d = SCAN_T / 2; d; d >>= 1) {
        if (tid < d) sm[tid] += sm[tid + d];
        __syncthreads();
    }
    if (tid == 0) g_bsum[blockIdx.x] = sm[0];
}

__global__ void k_scan_b(int nb) {
    __shared__ int sm[128];
    int tid = threadIdx.x;
    int v = (tid < nb) ? g_bsum[tid] : 0;
    sm[tid] = v;
    __syncthreads();
    for (int d = 1; d < 128; d <<= 1) {
        int t = (tid >= d) ? sm[tid - d] : 0;
        __syncthreads();
        sm[tid] += t;
        __syncthreads();
    }
    if (tid < nb) g_boff[tid] = sm[tid] - v;
}

__global__ void k_scan_c(int n) {
    __shared__ int sm[SCAN_T];
    int tid = threadIdx.x;
    int base = blockIdx.x * SCAN_TILE + tid * SCAN_C;
    int c[SCAN_C];
    int s = 0;
#pragma unroll
    for (int i = 0; i < SCAN_C; i++) {
        int idx = base + i;
        c[i] = (idx < n) ? g_cnt[idx] : 0;
        s += c[i];
    }
    sm[tid] = s;
    __syncthreads();
    for (int d = 1; d < SCAN_T; d <<= 1) {
        int t = (tid >= d) ? sm[tid - d] : 0;
        __syncthreads();
        sm[tid] += t;
        __syncthreads();
    }
    int run = g_boff[blockIdx.x] + sm[tid] - s;
#pragma unroll
    for (int i = 0; i < SCAN_C; i++) {
        int idx = base + i;
        if (idx < n) {
            g_rowptr[idx] = run;
            g_cursor[idx] = run;
            g_dinv[idx] = rsqrtf((float)(c[i] + 1));
            run += c[i];
        } else if (idx == n) {
            g_rowptr[n] = run;
        }
    }
}

// fill: vectorized int64 path (uint4 = 2 srcs / 2 dsts), 4 edges/thread/iter
__global__ void k_fill(const void* ei, long long E) {
    int is64 = g_idx64;
    if (is64 && ((E & 1) == 0)) {
        const uint4* s4 = (const uint4*)ei;                          // src row
        const uint4* d4 = (const uint4*)((const long long*)ei + E);  // dst row
        long long P = E >> 1;
        long long stride = (long long)gridDim.x * blockDim.x;
        long long i = (long long)blockIdx.x * blockDim.x + threadIdx.x;
        for (; i + stride < P; i += 2 * stride) {
            uint4 sa = s4[i];
            uint4 da = d4[i];
            uint4 sb = s4[i + stride];
            uint4 db = d4[i + stride];
            int p0 = atomicAdd(&g_cursor[da.x], 1);
            int p1 = atomicAdd(&g_cursor[da.z], 1);
            int p2 = atomicAdd(&g_cursor[db.x], 1);
            int p3 = atomicAdd(&g_cursor[db.z], 1);
            g_srcs[p0] = (int)sa.x;
            g_srcs[p1] = (int)sa.z;
            g_srcs[p2] = (int)sb.x;
            g_srcs[p3] = (int)sb.z;
        }
        for (; i < P; i += stride) {
            uint4 sa = s4[i];
            uint4 da = d4[i];
            int p0 = atomicAdd(&g_cursor[da.x], 1);
            int p1 = atomicAdd(&g_cursor[da.z], 1);
            g_srcs[p0] = (int)sa.x;
            g_srcs[p1] = (int)sa.z;
        }
    } else {
        long long stride = (long long)gridDim.x * blockDim.x;
        for (long long e = (long long)blockIdx.x * blockDim.x + threadIdx.x; e < E; e += stride) {
            int src = (int)ldidx(ei, e, is64);
            int dst = (int)ldidx(ei, E + e, is64);
            int p = atomicAdd(&g_cursor[dst], 1);
            g_srcs[p] = src;
        }
    }
}

// weights -> fp16 (W1 rows 0-127, W2 128-255, fcW1 256-383, fcW2 384-447)
__global__ void k_wconv(const float* __restrict__ W1, const float* __restrict__ W2,
                        const float* __restrict__ f1, const float* __restrict__ f2) {
    int i = blockIdx.x * blockDim.x + threadIdx.x;
    if (i >= 448 * DF) return;
    int r = i >> 7;
    float v;
    if (r < 128) v = W1[i];
    else if (r < 256) v = W2[i - 128 * DF];
    else if (r < 384) v = f1[i - 256 * DF];
    else v = f2[i - 384 * DF];
    g_wh[i] = __float2half_rn(v);
}

// ---------------- fp16 tensor-core GEMM (W already fp16) ----------------
#define LDA 36

__device__ __forceinline__ unsigned f2h2(float a, float b) {
    __half2 h = __floats2half2_rn(a, b);
    return *(unsigned*)&h;
}

__device__ __forceinline__ void mma_f16(float* d, const unsigned* a, const unsigned* b) {
    asm volatile(
        "mma.sync.aligned.m16n8k16.row.col.f32.f16.f16.f32 "
        "{%0,%1,%2,%3}, {%4,%5,%6,%7}, {%8,%9}, {%0,%1,%2,%3};\n"
        : "+f"(d[0]), "+f"(d[1]), "+f"(d[2]), "+f"(d[3])
        : "r"(a[0]), "r"(a[1]), "r"(a[2]), "r"(a[3]), "r"(b[0]), "r"(b[1]));
}

__device__ __forceinline__ float act_apply(float v, int ACT) {
    if (ACT == 1) return v > 0.f ? v : expm1f(v);
    return v;
}

// INH: A source half (else float). OUTH: store half (else float). Wh fp16.
template <int ACT, int INH, int OUTH>
__global__ __launch_bounds__(256, 2) void k_gemm_f16(
    const void* __restrict__ Av, const __half* __restrict__ Wh,
    const float* __restrict__ bias, void* __restrict__ Cv, int M) {
    __shared__ unsigned As[128 * LDA];
    __shared__ unsigned Ws[128 * LDA];
    int tid = threadIdx.x;
    int lane = tid & 31, warp = tid >> 5;
    int mw = warp & 1, nw = warp >> 1;
    int rowBase = blockIdx.x * 128;
    int g = lane >> 2, tig = lane & 3;

    float acc[4][4][4];
#pragma unroll
    for (int i = 0; i < 4; i++)
#pragma unroll
        for (int j = 0; j < 4; j++)
#pragma unroll
            for (int q = 0; q < 4; q++) acc[i][j][q] = 0.f;

#pragma unroll
    for (int ch = 0; ch < 2; ch++) {
        int kh = ch * 64;
#pragma unroll
        for (int i = 0; i < 4; i++) {
            int id = tid + i * 256;
            int r = id >> 3, c8 = (id & 7) * 4;
            if (INH) {
                uint4 u = make_uint4(0, 0, 0, 0);
                if (rowBase + r < M)
                    u = *(const uint4*)((const unsigned*)Av + (size_t)(rowBase + r) * (DF / 2) + kh / 2 + c8);
                *(uint4*)&As[r * LDA + c8] = u;
            } else {
                float4 v0 = make_float4(0.f, 0.f, 0.f, 0.f), v1 = v0;
                if (rowBase + r < M) {
                    const float* ap = (const float*)Av + (size_t)(rowBase + r) * DF + kh + c8 * 2;
                    v0 = *(const float4*)(ap);
                    v1 = *(const float4*)(ap + 4);
                }
                *(uint4*)&As[r * LDA + c8] = make_uint4(
                    f2h2(v0.x, v0.y), f2h2(v0.z, v0.w), f2h2(v1.x, v1.y), f2h2(v1.z, v1.w));
            }
            uint4 uw = *(const uint4*)((const unsigned*)Wh + (size_t)r * (DF / 2) + kh / 2 + c8);
            *(uint4*)&Ws[r * LDA + c8] = uw;
        }
        __syncthreads();

#pragma unroll
        for (int ks = 0; ks < 4; ks++) {
            int k0 = ks * 8;
            unsigned afr[4][4], bfr[4][2];
#pragma unroll
            for (int ma = 0; ma < 4; ma++) {
                int row = mw * 64 + ma * 16;
                afr[ma][0] = As[(row + g) * LDA + k0 + tig];
                afr[ma][1] = As[(row + g + 8) * LDA + k0 + tig];
                afr[ma][2] = As[(row + g) * LDA + k0 + tig + 4];
                afr[ma][3] = As[(row + g + 8) * LDA + k0 + tig + 4];
            }
#pragma unroll
            for (int na = 0; na < 4; na++) {
                int colw = nw * 32 + na * 8;
                bfr[na][0] = Ws[(colw + g) * LDA + k0 + tig];
                bfr[na][1] = Ws[(colw + g) * LDA + k0 + tig + 4];
            }
#pragma unroll
            for (int ma = 0; ma < 4; ma++)
#pragma unroll
                for (int na = 0; na < 4; na++) mma_f16(acc[ma][na], afr[ma], bfr[na]);
        }
        __syncthreads();
    }

#pragma unroll
    for (int ma = 0; ma < 4; ma++) {
        int r0 = rowBase + mw * 64 + ma * 16 + g;
        int r1 = r0 + 8;
#pragma unroll
        for (int na = 0; na < 4; na++) {
            int cc = nw * 32 + na * 8 + 2 * tig;
            float b0 = bias[cc], b1 = bias[cc + 1];
            float x0 = act_apply(acc[ma][na][0] + b0, ACT);
            float x1 = act_apply(acc[ma][na][1] + b1, ACT);
            float x2 = act_apply(acc[ma][na][2] + b0, ACT);
            float x3 = act_apply(acc[ma][na][3] + b1, ACT);
            if (OUTH) {
                __half* C = (__half*)Cv;
                if (r0 < M) *(__half2*)(C + (size_t)r0 * DF + cc) = __floats2half2_rn(x0, x1);
                if (r1 < M) *(__half2*)(C + (size_t)r1 * DF + cc) = __floats2half2_rn(x2, x3);
            } else {
                float* C = (float*)Cv;
                if (r0 < M) *(float2*)(C + (size_t)r0 * DF + cc) = make_float2(x0, x1);
                if (r1 < M) *(float2*)(C + (size_t)r1 * DF + cc) = make_float2(x2, x3);
            }
        }
    }
}

// ---------------- fp16 final GEMM (N=64) + fused log_softmax ----------------
__global__ __launch_bounds__(256, 2) void k_gemm_lsm_f16(
    const __half* __restrict__ A, const __half* __restrict__ Wh,
    const float* __restrict__ bias, float* __restrict__ out, int M) {
    __shared__ unsigned As[128 * LDA];
    __shared__ unsigned Ws[64 * LDA];
    int tid = threadIdx.x;
    int lane = tid & 31, warp = tid >> 5;
    int rowBase = blockIdx.x * 128;
    int g = lane >> 2, tig = lane & 3;

    float acc[8][4];
#pragma unroll
    for (int j = 0; j < 8; j++)
#pragma unroll
        for (int q = 0; q < 4; q++) acc[j][q] = 0.f;

#pragma unroll
    for (int ch = 0; ch < 2; ch++) {
        int kh = ch * 64;
#pragma unroll
        for (int i = 0; i < 4; i++) {
            int id = tid + i * 256;
            int r = id >> 3, c8 = (id & 7) * 4;
            uint4 u = make_uint4(0, 0, 0, 0);
            if (rowBase + r < M)
                u = *(const uint4*)((const unsigned*)A + (size_t)(rowBase + r) * (DF / 2) + kh / 2 + c8);
            *(uint4*)&As[r * LDA + c8] = u;
        }
#pragma unroll
        for (int i = 0; i < 2; i++) {
            int id = tid + i * 256;
            int r = id >> 3, c8 = (id & 7) * 4;
            uint4 uw = *(const uint4*)((const unsigned*)Wh + (size_t)r * (DF / 2) + kh / 2 + c8);
            *(uint4*)&Ws[r * LDA + c8] = uw;
        }
        __syncthreads();

#pragma unroll
        for (int ks = 0; ks < 4; ks++) {
            int k0 = ks * 8;
            unsigned afr[4], bfr[8][2];
            int row = warp * 16;
            afr[0] = As[(row + g) * LDA + k0 + tig];
            afr[1] = As[(row + g + 8) * LDA + k0 + tig];
            afr[2] = As[(row + g) * LDA + k0 + tig + 4];
            afr[3] = As[(row + g + 8) * LDA + k0 + tig + 4];
#pragma unroll
            for (int na = 0; na < 8; na++) {
                int colw = na * 8;
                bfr[na][0] = Ws[(colw + g) * LDA + k0 + tig];
                bfr[na][1] = Ws[(colw + g) * LDA + k0 + tig + 4];
            }
#pragma unroll
            for (int na = 0; na < 8; na++) mma_f16(acc[na], afr, bfr[na]);
        }
        __syncthreads();
    }

    float v0[16], v1[16];
#pragma unroll
    for (int na = 0; na < 8; na++) {
        int cc = na * 8 + 2 * tig;
        float b0 = bias[cc], b1 = bias[cc + 1];
        v0[na * 2 + 0] = acc[na][0] + b0;
        v0[na * 2 + 1] = acc[na][1] + b1;
        v1[na * 2 + 0] = acc[na][2] + b0;
        v1[na * 2 + 1] = acc[na][3] + b1;
    }
    float m0 = v0[0], m1 = v1[0];
#pragma unroll
    for (int i = 1; i < 16; i++) { m0 = fmaxf(m0, v0[i]); m1 = fmaxf(m1, v1[i]); }
#pragma unroll
    for (int d = 1; d < 4; d <<= 1) {
        m0 = fmaxf(m0, __shfl_xor_sync(0xffffffffu, m0, d));
        m1 = fmaxf(m1, __shfl_xor_sync(0xffffffffu, m1, d));
    }
    float s0 = 0.f, s1 = 0.f;
#pragma unroll
    for (int i = 0; i < 16; i++) { s0 += expf(v0[i] - m0); s1 += expf(v1[i] - m1); }
#pragma unroll
    for (int d = 1; d < 4; d <<= 1) {
        s0 += __shfl_xor_sync(0xffffffffu, s0, d);
        s1 += __shfl_xor_sync(0xffffffffu, s1, d);
    }
    float ls0 = m0 + logf(s0), ls1 = m1 + logf(s1);

    int r0 = rowBase + warp * 16 + g;
    int r1 = r0 + 8;
#pragma unroll
    for (int na = 0; na < 8; na++) {
        int cc = na * 8 + 2 * tig;
        if (r0 < M) {
            float2 o = make_float2(v0[na * 2] - ls0, v0[na * 2 + 1] - ls0);
            *(float2*)(out + (size_t)r0 * 64 + cc) = o;
        }
        if (r1 < M) {
            float2 o = make_float2(v1[na * 2] - ls1, v1[na * 2 + 1] - ls1);
            *(float2*)(out + (size_t)r1 * 64 + cc) = o;
        }
    }
}

// ---------------- aggregation over fp16 features ----------------
__global__ void k_agg_h(const uint2* __restrict__ zin, float* __restrict__ outf,
                        __half* __restrict__ outh, const float* __restrict__ bias,
                        int n, int relu) {
    int w = (blockIdx.x * blockDim.x + threadIdx.x) >> 5;
    int lane = threadIdx.x & 31;
    if (w >= n) return;
    float di = g_dinv[w];
    uint2 su = zin[(size_t)w * 32 + lane];
    float2 a0 = __half22float2(*(__half2*)&su.x);
    float2 a1 = __half22float2(*(__half2*)&su.y);
    float sw = di * di;
    float4 acc;
    acc.x = sw * a0.x; acc.y = sw * a0.y; acc.z = sw * a1.x; acc.w = sw * a1.y;
    int e = g_rowptr[w], end = g_rowptr[w + 1];
    for (; e + 4 <= end; e += 4) {
        int s[4];
        float wt[4];
#pragma unroll
        for (int i = 0; i < 4; i++) s[i] = g_srcs[e + i];
#pragma unroll
        for (int i = 0; i < 4; i++) wt[i] = di * g_dinv[s[i]];
        uint2 u[4];
#pragma unroll
        for (int i = 0; i < 4; i++) u[i] = zin[(size_t)s[i] * 32 + lane];
#pragma unroll
        for (int i = 0; i < 4; i++) {
            float2 f0 = __half22float2(*(__half2*)&u[i].x);
            float2 f1 = __half22float2(*(__half2*)&u[i].y);
            acc.x = fmaf(wt[i], f0.x, acc.x); acc.y = fmaf(wt[i], f0.y, acc.y);
            acc.z = fmaf(wt[i], f1.x, acc.z); acc.w = fmaf(wt[i], f1.y, acc.w);
        }
    }
    for (; e < end; e++) {
        int s = g_srcs[e];
        float wt = di * g_dinv[s];
        uint2 u = zin[(size_t)s * 32 + lane];
        float2 f0 = __half22float2(*(__half2*)&u.x);
        float2 f1 = __half22float2(*(__half2*)&u.y);
        acc.x = fmaf(wt, f0.x, acc.x); acc.y = fmaf(wt, f0.y, acc.y);
        acc.z = fmaf(wt, f1.x, acc.z); acc.w = fmaf(wt, f1.y, acc.w);
    }
    float4 b = ((const float4*)bias)[lane];
    acc.x += b.x; acc.y += b.y; acc.z += b.z; acc.w += b.w;
    if (relu) {
        acc.x = fmaxf(acc.x, 0.f); acc.y = fmaxf(acc.y, 0.f);
        acc.z = fmaxf(acc.z, 0.f); acc.w = fmaxf(acc.w, 0.f);
    }
    if (outf) ((float4*)outf)[(size_t)w * 32 + lane] = acc;
    if (outh) {
        uint2 o;
        __half2 h0 = __floats2half2_rn(acc.x, acc.y);
        __half2 h1 = __floats2half2_rn(acc.z, acc.w);
        o.x = *(unsigned*)&h0; o.y = *(unsigned*)&h1;
        ((uint2*)outh)[(size_t)w * 32 + lane] = o;
    }
}

// ---------------- launcher ----------------
extern "C" void kernel_launch(void* const* d_in, const int* in_sizes, int n_in,
                              void* d_out, int out_size) {
    const float* x    = (const float*)d_in[0];
    const void*  ei   = d_in[1];
    const float* W1   = (const float*)d_in[2];
    const float* b1   = (const float*)d_in[3];
    const float* W2   = (const float*)d_in[4];
    const float* b2   = (const float*)d_in[5];
    const float* fcW1 = (const float*)d_in[6];
    const float* fcb1 = (const float*)d_in[7];
    const float* fcW2 = (const float*)d_in[8];
    const float* fcb2 = (const float*)d_in[9];

    int N = in_sizes[0] / DF;
    long long E = (long long)in_sizes[1] / 2;

    float *zsb, *resb, *zb;
    __half *z0h, *z1h, *zsh, *wh;
    int* cntp;
    cudaGetSymbolAddress((void**)&z0h, g_z0h);
    cudaGetSymbolAddress((void**)&z1h, g_z1h);
    cudaGetSymbolAddress((void**)&zsh, g_zsh);
    cudaGetSymbolAddress((void**)&wh,  g_wh);
    cudaGetSymbolAddress((void**)&zsb, g_zs);
    cudaGetSymbolAddress((void**)&resb, g_res);
    cudaGetSymbolAddress((void**)&zb,  g_zerob);
    cudaGetSymbolAddress((void**)&cntp, g_cnt);

    const __half* whW1 = wh;
    const __half* whW2 = wh + 128 * DF;
    const __half* whF1 = wh + 256 * DF;
    const __half* whF2 = wh + 384 * DF;

    // Output layout: tuple (zs [N,128], res [N,64]) concatenated.
    float* zs_out;
    float* res_out;
    long long need_both = (long long)N * (DF + 64);
    if ((long long)out_size >= need_both) {
        zs_out = (float*)d_out;
        res_out = (float*)d_out + (size_t)N * DF;
    } else if (out_size == N * 64) {
        zs_out = zsb;
        res_out = (float*)d_out;
    } else {
        zs_out = (float*)d_out;
        res_out = resb;
    }

    // edge kernels: 4 edges/thread (vectorized int64 path)
    int nb_e = (int)((E / 4 + 255) / 256);
    if (nb_e < 148) nb_e = 148;
    int nb_w = (N * 32 + 255) / 256;
    int nb_g = (N + 127) / 128;
    int nb_s = (N + 1 + SCAN_TILE - 1) / SCAN_TILE;

    static cudaStream_t s2 = nullptr;
    static cudaEvent_t evFork = nullptr, evJoin = nullptr;
    if (s2 == nullptr) {
        cudaStreamCreateWithFlags(&s2, cudaStreamNonBlocking);
        cudaEventCreateWithFlags(&evFork, cudaEventDisableTiming);
        cudaEventCreateWithFlags(&evJoin, cudaEventDisableTiming);
    }

    // fork: preprocessing branch on s2, gemm branch on default stream
    cudaEventRecord(evFork, 0);
    cudaStreamWaitEvent(s2, evFork, 0);

    // s2: graph preprocessing (CSR build)
    k_detect<<<1, 256, 0, s2>>>(ei, E);
    cudaMemsetAsync(cntp, 0, (size_t)N * sizeof(int), s2);
    k_count<<<nb_e, 256, 0, s2>>>(ei, E);
    k_scan_a<<<nb_s, SCAN_T, 0, s2>>>(N);
    k_scan_b<<<1, 128, 0, s2>>>(nb_s);
    k_scan_c<<<nb_s, SCAN_T, 0, s2>>>(N);
    k_fill<<<nb_e, 256, 0, s2>>>(ei, E);
    cudaEventRecord(evJoin, s2);

    // default: weight conversion + gemm1 (independent of graph build)
    k_wconv<<<(448 * DF + 255) / 256, 256>>>(W1, W2, fcW1, fcW2);
    k_gemm_f16<0, 0, 1><<<nb_g, 256>>>(x, whW1, zb, z0h, N);

    // join
    cudaStreamWaitEvent(0, evJoin, 0);

    // layer 1: z1h = relu(agg(x @ W1^T) + b1)
    k_agg_h<<<nb_w, 256>>>((const uint2*)z0h, nullptr, z1h, b1, N, 1);

    // layer 2: zs = agg(z1 @ W2^T) + b2
    k_gemm_f16<0, 1, 1><<<nb_g, 256>>>(z1h, whW2, zb, z0h, N);
    k_agg_h<<<nb_w, 256>>>((const uint2*)z0h, zs_out, zsh, b2, N, 0);

    // projection: h = elu(zs @ fcW1^T + fcb1); res = log_softmax(h @ fcW2^T + fcb2)
    k_gemm_f16<1, 1, 1><<<nb_g, 256>>>(zsh, whF1, fcb1, z0h, N);
    k_gemm_lsm_f16<<<nb_g, 256>>>(z0h, whF2, fcb2, res_out, N);
}